// round 7
// baseline (speedup 1.0000x reference)
#include <cuda_runtime.h>

// Problem shape (from reference): x [B=32, T=4096, C=128] float32.
// Output layout (pytree flatten of (low, [res, 0, 0])): [low | res | zeros | zeros],
// each B*T*C floats.

#define BB 32
#define TT 4096
#define CC 128
#define C4N (CC / 4)                  // 32 float4 groups per row
#define NCH2 256                      // sub-chunks per batch (warp-private)
#define RPW 16                        // rows per sub-chunk
#define BTC ((size_t)BB * TT * CC)    // 16,777,216

// Scratch (no cudaMalloc allowed): partial moments + coefficients
__device__ float g_partial[BB * NCH2 * 3 * CC];     // 12 MB
__device__ float g_coef[BB * 3 * CC];               // 48 KB

struct Ginv9 { float g[9]; };

// ---------------------------------------------------------------------------
// Phase 1: per-(b, sub-chunk) partial moments. Each warp owns a private
// 16-row sub-chunk; each lane covers 4 channels via float4 (warp row = 512 B,
// fully coalesced). Per channel, one lane sums its 16 rows in fixed order ->
// bitwise deterministic. Default cache policy so x lines populate L2 for
// phase 3.
// ---------------------------------------------------------------------------
__global__ void __launch_bounds__(128) moments_kernel(const float* __restrict__ x) {
    const unsigned blk   = blockIdx.x;            // b * 64 + chunk
    const unsigned b     = blk >> 6;
    const unsigned chunk = blk & 63;
    const unsigned w     = threadIdx.x >> 5;      // warp 0..3
    const unsigned lane  = threadIdx.x & 31;

    const unsigned row0 = chunk * 64 + w * RPW;   // first row of this warp's sub-chunk
    const float4* __restrict__ xp = reinterpret_cast<const float4*>(
        x + ((size_t)b * TT + row0) * CC) + lane;

    const float inv = 1.0f / (float)(TT - 1);
    float4 s0 = make_float4(0.f, 0.f, 0.f, 0.f);
    float4 s1 = s0, s2 = s0;

#pragma unroll
    for (int i = 0; i < RPW; ++i) {
        const float4 v = xp[(size_t)i * C4N];
        const float t  = (float)(row0 + i) * inv;
        const float t2 = t * t;
        s0.x += v.x; s0.y += v.y; s0.z += v.z; s0.w += v.w;
        s1.x = fmaf(v.x, t, s1.x);  s1.y = fmaf(v.y, t, s1.y);
        s1.z = fmaf(v.z, t, s1.z);  s1.w = fmaf(v.w, t, s1.w);
        s2.x = fmaf(v.x, t2, s2.x); s2.y = fmaf(v.y, t2, s2.y);
        s2.z = fmaf(v.z, t2, s2.z); s2.w = fmaf(v.w, t2, s2.w);
    }

    const unsigned pidx = blk * 4 + w;            // b * NCH2 + sub-chunk
    float4* __restrict__ p = reinterpret_cast<float4*>(
        g_partial + ((size_t)pidx * 3) * CC) + lane;
    p[0 * C4N] = s0;
    p[1 * C4N] = s1;
    p[2 * C4N] = s2;
}

// ---------------------------------------------------------------------------
// Phase 2: reduce 256 partials per (b, 4-channel group), apply inverse Gram.
// 1024 threads; fixed-order sum -> deterministic. Reads 12 MB (negligible).
// ---------------------------------------------------------------------------
__global__ void __launch_bounds__(128) coef_kernel(Ginv9 gi) {
    const unsigned idx = blockIdx.x * blockDim.x + threadIdx.x;  // 0..B*C4N-1
    if (idx >= BB * C4N) return;
    const unsigned b  = idx / C4N;
    const unsigned c4 = idx % C4N;

    float4 m0 = make_float4(0.f, 0.f, 0.f, 0.f);
    float4 m1 = m0, m2 = m0;
#pragma unroll 8
    for (int k = 0; k < NCH2; ++k) {
        const float4* __restrict__ p = reinterpret_cast<const float4*>(
            g_partial + ((size_t)(b * NCH2 + k) * 3) * CC) + c4;
        const float4 a0 = p[0 * C4N], a1 = p[1 * C4N], a2 = p[2 * C4N];
        m0.x += a0.x; m0.y += a0.y; m0.z += a0.z; m0.w += a0.w;
        m1.x += a1.x; m1.y += a1.y; m1.z += a1.z; m1.w += a1.w;
        m2.x += a2.x; m2.y += a2.y; m2.z += a2.z; m2.w += a2.w;
    }

    float4 c0, c1, c2;
    c0.x = gi.g[0]*m0.x + gi.g[1]*m1.x + gi.g[2]*m2.x;
    c0.y = gi.g[0]*m0.y + gi.g[1]*m1.y + gi.g[2]*m2.y;
    c0.z = gi.g[0]*m0.z + gi.g[1]*m1.z + gi.g[2]*m2.z;
    c0.w = gi.g[0]*m0.w + gi.g[1]*m1.w + gi.g[2]*m2.w;
    c1.x = gi.g[3]*m0.x + gi.g[4]*m1.x + gi.g[5]*m2.x;
    c1.y = gi.g[3]*m0.y + gi.g[4]*m1.y + gi.g[5]*m2.y;
    c1.z = gi.g[3]*m0.z + gi.g[4]*m1.z + gi.g[5]*m2.z;
    c1.w = gi.g[3]*m0.w + gi.g[4]*m1.w + gi.g[5]*m2.w;
    c2.x = gi.g[6]*m0.x + gi.g[7]*m1.x + gi.g[8]*m2.x;
    c2.y = gi.g[6]*m0.y + gi.g[7]*m1.y + gi.g[8]*m2.y;
    c2.z = gi.g[6]*m0.z + gi.g[7]*m1.z + gi.g[8]*m2.z;
    c2.w = gi.g[6]*m0.w + gi.g[7]*m1.w + gi.g[8]*m2.w;

    float4* __restrict__ cf = reinterpret_cast<float4*>(
        g_coef + ((size_t)b * 3) * CC) + c4;
    cf[0 * C4N] = c0;
    cf[1 * C4N] = c1;
    cf[2 * C4N] = c2;
}

// ---------------------------------------------------------------------------
// Phase 3: evaluate trend, residual, and zero-fill highs[1..2].
// Each thread handles 2 adjacent float4 groups per iteration (coalesced
// 32 B/lane): 2 loads (targeting L2-hit on x) + 8 x 16B streaming stores.
// __stcs on stores -> evict-first: output lines don't displace x in L2.
// ---------------------------------------------------------------------------
__global__ void __launch_bounds__(256) output_kernel(const float* __restrict__ x,
                                                     float* __restrict__ out) {
    const size_t ngroups = BTC / 4;               // 4,194,304 float4 groups
    const size_t base = ((size_t)blockIdx.x * blockDim.x + threadIdx.x) * 2;
    if (base >= ngroups) return;

    float4* __restrict__ o = reinterpret_cast<float4*>(out);
    const float4* __restrict__ xi = reinterpret_cast<const float4*>(x);
    const float4 z = make_float4(0.f, 0.f, 0.f, 0.f);

#pragma unroll
    for (int u = 0; u < 2; ++u) {
        const size_t i = base + u;

        const unsigned c4 = (unsigned)(i & (C4N - 1));
        const size_t   bt = i / C4N;              // b*T + t
        const unsigned t  = (unsigned)(bt & (TT - 1));
        const unsigned b  = (unsigned)(bt >> 12); // /TT

        // Independent zero stores first: overlap with the x load.
        __stcs(&o[i + 2 * (BTC / 4)], z);
        __stcs(&o[i + 3 * (BTC / 4)], z);

        const float tn = (float)t * (1.0f / (float)(TT - 1));

        // Last use of x: streaming load (don't re-protect in L2 after this).
        const float4 xv = __ldcs(&xi[i]);

        const float4* __restrict__ cf =
            reinterpret_cast<const float4*>(g_coef) + (size_t)b * 3 * C4N + c4;
        const float4 k0 = cf[0 * C4N];
        const float4 k1 = cf[1 * C4N];
        const float4 k2 = cf[2 * C4N];

        float4 low;
        low.x = fmaf(tn, fmaf(tn, k2.x, k1.x), k0.x);
        low.y = fmaf(tn, fmaf(tn, k2.y, k1.y), k0.y);
        low.z = fmaf(tn, fmaf(tn, k2.z, k1.z), k0.z);
        low.w = fmaf(tn, fmaf(tn, k2.w, k1.w), k0.w);

        float4 res;
        res.x = xv.x - low.x;
        res.y = xv.y - low.y;
        res.z = xv.z - low.z;
        res.w = xv.w - low.w;

        __stcs(&o[i], low);
        __stcs(&o[i + 1 * (BTC / 4)], res);
    }
}

// ---------------------------------------------------------------------------
// Host: inverse Gram matrix in double, then launch pipeline.
// ---------------------------------------------------------------------------
extern "C" void kernel_launch(void* const* d_in, const int* in_sizes, int n_in,
                              void* d_out, int out_size) {
    (void)in_sizes; (void)n_in; (void)out_size;
    const float* x   = (const float*)d_in[0];
    float*       out = (float*)d_out;

    // G[i][j] = sum_t t^(i+j), t = k/(T-1)  (exact in double)
    double S[5] = {0, 0, 0, 0, 0};
    for (int k = 0; k < TT; ++k) {
        double t = (double)k / (double)(TT - 1);
        double p = 1.0;
        for (int e = 0; e < 5; ++e) { S[e] += p; p *= t; }
    }
    const double a = S[0], b = S[1], c = S[2];
    const double d = S[1], e = S[2], f = S[3];
    const double g = S[2], h = S[3], ii = S[4];
    const double det = a * (e * ii - f * h) - b * (d * ii - f * g) + c * (d * h - e * g);
    const double id = 1.0 / det;

    Ginv9 gi;
    gi.g[0] = (float)((e * ii - f * h) * id);
    gi.g[1] = (float)((c * h - b * ii) * id);
    gi.g[2] = (float)((b * f - c * e) * id);
    gi.g[3] = (float)((f * g - d * ii) * id);
    gi.g[4] = (float)((a * ii - c * g) * id);
    gi.g[5] = (float)((c * d - a * f) * id);
    gi.g[6] = (float)((d * h - e * g) * id);
    gi.g[7] = (float)((b * g - a * h) * id);
    gi.g[8] = (float)((a * e - b * d) * id);

    moments_kernel<<<BB * 64, 128>>>(x);
    coef_kernel<<<(BB * C4N + 127) / 128, 128>>>(gi);
    const size_t ngroups = BTC / 4;                       // pairs = ngroups/2
    output_kernel<<<(unsigned)(ngroups / 2 / 256), 256>>>(x, out);
}

// round 14
// speedup vs baseline: 1.3735x; 1.3735x over previous
#include <cuda_runtime.h>

// Problem shape (from reference): x [B=32, T=4096, C=128] float32.
// Output layout (pytree flatten of (low, [res, 0, 0])): [low | res | zeros | zeros],
// each B*T*C floats.

#define BB 32
#define TT 4096
#define CC 128
#define C4N (CC / 4)                  // 32 float4 groups per row
#define NCH2 512                      // sub-chunks per batch (warp-private)
#define RPW 8                         // rows per sub-chunk
#define NBLK_PER_B 128                // moment blocks per batch (4 warps x 8 rows = 32 rows)
#define BTC ((size_t)BB * TT * CC)    // 16,777,216

// Scratch (no cudaMalloc allowed): partial moments + coefficients
__device__ float g_partial[BB * NCH2 * 3 * CC];     // ~25 MB
__device__ float g_coef[BB * 3 * CC];               // 48 KB

struct Ginv9 { float g[9]; };

// ---------------------------------------------------------------------------
// Phase 1 (was 16us @4.3TB/s with 2048 CTAs, 57% occ -> latency/tail-bound):
// now 4096 CTAs, each warp owns an 8-row sub-chunk; each lane covers 4
// channels via float4 (warp row = 512 B, fully coalesced). Fixed order ->
// deterministic.
// ---------------------------------------------------------------------------
__global__ void __launch_bounds__(128) moments_kernel(const float* __restrict__ x) {
    const unsigned blk   = blockIdx.x;            // b * 128 + chunk
    const unsigned b     = blk >> 7;
    const unsigned chunk = blk & (NBLK_PER_B - 1);
    const unsigned w     = threadIdx.x >> 5;      // warp 0..3
    const unsigned lane  = threadIdx.x & 31;

    const unsigned row0 = chunk * 32 + w * RPW;   // first row of this warp's sub-chunk
    const float4* __restrict__ xp = reinterpret_cast<const float4*>(
        x + ((size_t)b * TT + row0) * CC) + lane;

    const float inv = 1.0f / (float)(TT - 1);
    float4 s0 = make_float4(0.f, 0.f, 0.f, 0.f);
    float4 s1 = s0, s2 = s0;

#pragma unroll
    for (int i = 0; i < RPW; ++i) {
        const float4 v = xp[(size_t)i * C4N];
        const float t  = (float)(row0 + i) * inv;
        const float t2 = t * t;
        s0.x += v.x; s0.y += v.y; s0.z += v.z; s0.w += v.w;
        s1.x = fmaf(v.x, t, s1.x);  s1.y = fmaf(v.y, t, s1.y);
        s1.z = fmaf(v.z, t, s1.z);  s1.w = fmaf(v.w, t, s1.w);
        s2.x = fmaf(v.x, t2, s2.x); s2.y = fmaf(v.y, t2, s2.y);
        s2.z = fmaf(v.z, t2, s2.z); s2.w = fmaf(v.w, t2, s2.w);
    }

    const unsigned pidx = blk * 4 + w;            // = b * NCH2 + (chunk*4 + w)
    float4* __restrict__ p = reinterpret_cast<float4*>(
        g_partial + ((size_t)pidx * 3) * CC) + lane;
    p[0 * C4N] = s0;
    p[1 * C4N] = s1;
    p[2 * C4N] = s2;
}

// ---------------------------------------------------------------------------
// Phase 2: reduce 512 partials per (b, 4-channel group), apply inverse Gram.
// 1024 threads in 32 blocks of 32 -> reduction LSU work spread over 32 SMs
// (g_partial is L2-resident; it was just written). Fixed-order -> determin.
// ---------------------------------------------------------------------------
__global__ void __launch_bounds__(32) coef_kernel(Ginv9 gi) {
    const unsigned idx = blockIdx.x * 32 + threadIdx.x;  // 0..B*C4N-1
    const unsigned b  = idx / C4N;
    const unsigned c4 = idx % C4N;

    float4 m0 = make_float4(0.f, 0.f, 0.f, 0.f);
    float4 m1 = m0, m2 = m0;
#pragma unroll 8
    for (int k = 0; k < NCH2; ++k) {
        const float4* __restrict__ p = reinterpret_cast<const float4*>(
            g_partial + ((size_t)(b * NCH2 + k) * 3) * CC) + c4;
        const float4 a0 = p[0 * C4N], a1 = p[1 * C4N], a2 = p[2 * C4N];
        m0.x += a0.x; m0.y += a0.y; m0.z += a0.z; m0.w += a0.w;
        m1.x += a1.x; m1.y += a1.y; m1.z += a1.z; m1.w += a1.w;
        m2.x += a2.x; m2.y += a2.y; m2.z += a2.z; m2.w += a2.w;
    }

    float4 c0, c1, c2;
    c0.x = gi.g[0]*m0.x + gi.g[1]*m1.x + gi.g[2]*m2.x;
    c0.y = gi.g[0]*m0.y + gi.g[1]*m1.y + gi.g[2]*m2.y;
    c0.z = gi.g[0]*m0.z + gi.g[1]*m1.z + gi.g[2]*m2.z;
    c0.w = gi.g[0]*m0.w + gi.g[1]*m1.w + gi.g[2]*m2.w;
    c1.x = gi.g[3]*m0.x + gi.g[4]*m1.x + gi.g[5]*m2.x;
    c1.y = gi.g[3]*m0.y + gi.g[4]*m1.y + gi.g[5]*m2.y;
    c1.z = gi.g[3]*m0.z + gi.g[4]*m1.z + gi.g[5]*m2.z;
    c1.w = gi.g[3]*m0.w + gi.g[4]*m1.w + gi.g[5]*m2.w;
    c2.x = gi.g[6]*m0.x + gi.g[7]*m1.x + gi.g[8]*m2.x;
    c2.y = gi.g[6]*m0.y + gi.g[7]*m1.y + gi.g[8]*m2.y;
    c2.z = gi.g[6]*m0.z + gi.g[7]*m1.z + gi.g[8]*m2.z;
    c2.w = gi.g[6]*m0.w + gi.g[7]*m1.w + gi.g[8]*m2.w;

    float4* __restrict__ cf = reinterpret_cast<float4*>(
        g_coef + ((size_t)b * 3) * CC) + c4;
    cf[0 * C4N] = c0;
    cf[1 * C4N] = c1;
    cf[2 * C4N] = c2;
}

// ---------------------------------------------------------------------------
// Phase 3 (FIX vs 163us baseline: was ~144us @ ~2.2TB/s from strided stores):
// one float4 group per thread, consecutive threads -> consecutive 16B
// addresses. Each warp store = one contiguous 512 B segment per output
// stream (full-line wavefronts). 1 load (L2-hit target) + 4 streaming stores.
// ---------------------------------------------------------------------------
__global__ void __launch_bounds__(256) output_kernel(const float* __restrict__ x,
                                                     float* __restrict__ out) {
    const size_t i = (size_t)blockIdx.x * blockDim.x + threadIdx.x;  // float4 group

    const unsigned c4 = (unsigned)(i & (C4N - 1));
    const size_t   bt = i >> 5;               // / C4N: b*T + t
    const unsigned t  = (unsigned)(bt & (TT - 1));
    const unsigned b  = (unsigned)(bt >> 12); // / TT

    float4* __restrict__ o = reinterpret_cast<float4*>(out);
    const float4 z = make_float4(0.f, 0.f, 0.f, 0.f);

    // Independent zero stores first: overlap with the x load.
    __stcs(&o[i + 2 * (BTC / 4)], z);
    __stcs(&o[i + 3 * (BTC / 4)], z);

    const float tn = (float)t * (1.0f / (float)(TT - 1));

    // Last use of x: streaming load (evict-first; still hits if resident).
    const float4 xv = __ldcs(&reinterpret_cast<const float4*>(x)[i]);

    const float4* __restrict__ cf =
        reinterpret_cast<const float4*>(g_coef) + (size_t)b * 3 * C4N + c4;
    const float4 k0 = cf[0 * C4N];
    const float4 k1 = cf[1 * C4N];
    const float4 k2 = cf[2 * C4N];

    float4 low;
    low.x = fmaf(tn, fmaf(tn, k2.x, k1.x), k0.x);
    low.y = fmaf(tn, fmaf(tn, k2.y, k1.y), k0.y);
    low.z = fmaf(tn, fmaf(tn, k2.z, k1.z), k0.z);
    low.w = fmaf(tn, fmaf(tn, k2.w, k1.w), k0.w);

    float4 res;
    res.x = xv.x - low.x;
    res.y = xv.y - low.y;
    res.z = xv.z - low.z;
    res.w = xv.w - low.w;

    __stcs(&o[i], low);
    __stcs(&o[i + 1 * (BTC / 4)], res);
}

// ---------------------------------------------------------------------------
// Host: inverse Gram matrix in double, then launch pipeline.
// ---------------------------------------------------------------------------
extern "C" void kernel_launch(void* const* d_in, const int* in_sizes, int n_in,
                              void* d_out, int out_size) {
    (void)in_sizes; (void)n_in; (void)out_size;
    const float* x   = (const float*)d_in[0];
    float*       out = (float*)d_out;

    // G[i][j] = sum_t t^(i+j), t = k/(T-1)  (exact in double)
    double S[5] = {0, 0, 0, 0, 0};
    for (int k = 0; k < TT; ++k) {
        double t = (double)k / (double)(TT - 1);
        double p = 1.0;
        for (int e = 0; e < 5; ++e) { S[e] += p; p *= t; }
    }
    const double a = S[0], b = S[1], c = S[2];
    const double d = S[1], e = S[2], f = S[3];
    const double g = S[2], h = S[3], ii = S[4];
    const double det = a * (e * ii - f * h) - b * (d * ii - f * g) + c * (d * h - e * g);
    const double id = 1.0 / det;

    Ginv9 gi;
    gi.g[0] = (float)((e * ii - f * h) * id);
    gi.g[1] = (float)((c * h - b * ii) * id);
    gi.g[2] = (float)((b * f - c * e) * id);
    gi.g[3] = (float)((f * g - d * ii) * id);
    gi.g[4] = (float)((a * ii - c * g) * id);
    gi.g[5] = (float)((c * d - a * f) * id);
    gi.g[6] = (float)((d * h - e * g) * id);
    gi.g[7] = (float)((b * g - a * h) * id);
    gi.g[8] = (float)((a * e - b * d) * id);

    moments_kernel<<<BB * NBLK_PER_B, 128>>>(x);
    coef_kernel<<<(BB * C4N) / 32, 32>>>(gi);
    const size_t ngroups = BTC / 4;                       // 4,194,304
    output_kernel<<<(unsigned)(ngroups / 256), 256>>>(x, out);
}